// round 12
// baseline (speedup 1.0000x reference)
#include <cuda_runtime.h>

#define SEQ 100
#define NF  18
#define HD  16
#define WPC 2        // warps per CTA (64 threads)
#define BPW 8        // batches per warp (4 per half)
#define XROWS 8      // xs row stride (floats), 32B
#define H1R 12       // h1d row stride (floats), 48B: conflict-free STS.128
#define H2R 8        // h2d row stride (floats), 32B (smem budget)

typedef unsigned long long u64;

struct __align__(16) Smem {
    float4 w1[NF + HD][HD];   // rows 0..17: Wih1, 18..33: Whh1; [row][j]=(wi,wf,wg,wo)
    float4 w2[2 * HD][HD];    // rows 0..15: Wih2, 16..31: Whh2
    float4 bia1[HD];
    float4 bia2[HD];
    float  xs [WPC][4][NF][XROWS];   // 4 timestep slots, batch-packed
    float  h1d[WPC][2][HD][H1R];     // double-buffered h1 (pre-relu)
    float  h2d[WPC][2][HD][H2R];     // double-buffered h2
};

__device__ __forceinline__ u64 ffma2(u64 a, u64 b, u64 c) {
    u64 d;
    asm("fma.rn.f32x2 %0, %1, %2, %3;" : "=l"(d) : "l"(a), "l"(b), "l"(c));
    return d;
}
__device__ __forceinline__ u64 dup2(float v) {
    u64 d;
    asm("mov.b64 %0, {%1, %1};" : "=l"(d) : "f"(v));
    return d;
}
__device__ __forceinline__ u64 pack2(float lo, float hi) {
    u64 d;
    asm("mov.b64 %0, {%1, %2};" : "=l"(d) : "f"(lo), "f"(hi));
    return d;
}
__device__ __forceinline__ float2 unpk(u64 v) {
    float2 r;
    asm("mov.b64 {%0, %1}, %2;" : "=f"(r.x), "=f"(r.y) : "l"(v));
    return r;
}
__device__ __forceinline__ float sigf(float x) {
    float e = __expf(-x);
    return __fdividef(1.f, 1.f + e);
}
// overflow-safe tanh: tanh(x) = sign(x) * (1 - 2/(exp(2|x|)+1))
__device__ __forceinline__ float tanhfast(float x) {
    float a = fabsf(x);
    float e = __expf(2.f * a);
    float t = 1.f - __fdividef(2.f, e + 1.f);
    return x < 0.f ? -t : t;
}

// one k-row: 1 LDS.128 weight (gate-packed), 4 ALU dups, 1 LDS.128 operand
// (batch-packed, 4 batches), 8 FFMA2
#define KSTEP(AI0,AI1,AF0,AF1,AG0,AG1,AO0,AO1, WPTR, OPPTR) do {        \
    float4 _w = *(const float4*)(WPTR);                                 \
    u64 _wi = dup2(_w.x), _wf = dup2(_w.y);                             \
    u64 _wg = dup2(_w.z), _wo = dup2(_w.w);                             \
    ulonglong2 _o = *(const ulonglong2*)(OPPTR);                        \
    AI0 = ffma2(_o.x, _wi, AI0);  AI1 = ffma2(_o.y, _wi, AI1);          \
    AF0 = ffma2(_o.x, _wf, AF0);  AF1 = ffma2(_o.y, _wf, AF1);          \
    AG0 = ffma2(_o.x, _wg, AG0);  AG1 = ffma2(_o.y, _wg, AG1);          \
    AO0 = ffma2(_o.x, _wo, AO0);  AO1 = ffma2(_o.y, _wo, AO1);          \
} while (0)

// same, with in-register relu on the operand (layer-2 input path)
#define KSTEPR(AI0,AI1,AF0,AF1,AG0,AG1,AO0,AO1, WPTR, OPPTR) do {       \
    float4 _w = *(const float4*)(WPTR);                                 \
    u64 _wi = dup2(_w.x), _wf = dup2(_w.y);                             \
    u64 _wg = dup2(_w.z), _wo = dup2(_w.w);                             \
    float4 _q = *(const float4*)(OPPTR);                                \
    u64 _o0 = pack2(fmaxf(_q.x, 0.f), fmaxf(_q.y, 0.f));                \
    u64 _o1 = pack2(fmaxf(_q.z, 0.f), fmaxf(_q.w, 0.f));                \
    AI0 = ffma2(_o0, _wi, AI0);  AI1 = ffma2(_o1, _wi, AI1);            \
    AF0 = ffma2(_o0, _wf, AF0);  AF1 = ffma2(_o1, _wf, AF1);            \
    AG0 = ffma2(_o0, _wg, AG0);  AG1 = ffma2(_o1, _wg, AG1);            \
    AO0 = ffma2(_o0, _wo, AO0);  AO1 = ffma2(_o1, _wo, AO1);            \
} while (0)

__global__ void __launch_bounds__(64, 7)
lstm2_kernel(const float* __restrict__ x,
             const float* __restrict__ Wih1, const float* __restrict__ Whh1,
             const float* __restrict__ bih1, const float* __restrict__ bhh1,
             const float* __restrict__ Wih2, const float* __restrict__ Whh2,
             const float* __restrict__ bih2, const float* __restrict__ bhh2,
             float* __restrict__ out)
{
    extern __shared__ Smem sm[];
    Smem& s = sm[0];
    const int tid = threadIdx.x;

    // ---- one-time weight prep: gate-packed [row][j] float4 ----
    for (int i = tid; i < (NF + HD) * HD; i += 64) {
        int row = i / HD, j = i % HD;
        float4 w;
        if (row < NF) {
            int k = row;
            w = make_float4(Wih1[j * NF + k],        Wih1[(16 + j) * NF + k],
                            Wih1[(32 + j) * NF + k], Wih1[(48 + j) * NF + k]);
        } else {
            int k = row - NF;
            w = make_float4(Whh1[j * HD + k],        Whh1[(16 + j) * HD + k],
                            Whh1[(32 + j) * HD + k], Whh1[(48 + j) * HD + k]);
        }
        s.w1[row][j] = w;
    }
    for (int i = tid; i < 2 * HD * HD; i += 64) {
        int row = i / HD, j = i % HD;
        float4 w;
        if (row < HD) {
            int k = row;
            w = make_float4(Wih2[j * HD + k],        Wih2[(16 + j) * HD + k],
                            Wih2[(32 + j) * HD + k], Wih2[(48 + j) * HD + k]);
        } else {
            int k = row - HD;
            w = make_float4(Whh2[j * HD + k],        Whh2[(16 + j) * HD + k],
                            Whh2[(32 + j) * HD + k], Whh2[(48 + j) * HD + k]);
        }
        s.w2[row][j] = w;
    }
    if (tid < HD) {
        int j = tid;
        s.bia1[j] = make_float4(bih1[j] + bhh1[j],           bih1[16 + j] + bhh1[16 + j],
                                bih1[32 + j] + bhh1[32 + j], bih1[48 + j] + bhh1[48 + j]);
        s.bia2[j] = make_float4(bih2[j] + bhh2[j],           bih2[16 + j] + bhh2[16 + j],
                                bih2[32 + j] + bhh2[32 + j], bih2[48 + j] + bhh2[48 + j]);
    }
    __syncthreads();

    const int warp = tid >> 5;
    const int lane = tid & 31;
    const int half = lane >> 4;
    const int j    = lane & 15;
    const int b0   = half * 4;
    const long warpBatch = (long)(blockIdx.x * WPC + warp) * BPW;
    const float* xbase = x + warpBatch * (long)(SEQ * NF);

    // zero h buffers (parity 0, read at t=0)
    {
        float4 z = make_float4(0.f, 0.f, 0.f, 0.f);
        *(float4*)&s.h1d[warp][0][j][b0] = z;
        *(float4*)&s.h2d[warp][0][j][b0] = z;
    }
    float c1[4] = {0.f, 0.f, 0.f, 0.f};
    float c2[4] = {0.f, 0.f, 0.f, 0.f};
    float h2v[4] = {0.f, 0.f, 0.f, 0.f};

    // bias registers (duplicated)
    float4 bv1 = s.bia1[j];
    float4 bv2 = s.bia2[j];
    const u64 BI1 = dup2(bv1.x), BF1 = dup2(bv1.y), BG1 = dup2(bv1.z), BO1 = dup2(bv1.w);
    const u64 BI2 = dup2(bv2.x), BF2 = dup2(bv2.y), BG2 = dup2(bv2.z), BO2 = dup2(bv2.w);

    // ---- x staging: 4 steps [s0..s0+3] (s0 % 4 == 0 -> 16B-aligned float4) ----
    auto stage = [&](int s0) {
        for (int i = lane; i < BPW * NF; i += 32) {      // 144 float4
            int b = i / NF, m = i % NF;
            float4 v = *(const float4*)(xbase + (long)b * (SEQ * NF) + s0 * NF + m * 4);
            int pos = m * 4;
            s.xs[warp][(pos    ) / NF][(pos    ) % NF][b] = v.x;
            s.xs[warp][(pos + 1) / NF][(pos + 1) % NF][b] = v.y;
            s.xs[warp][(pos + 2) / NF][(pos + 2) % NF][b] = v.z;
            s.xs[warp][(pos + 3) / NF][(pos + 3) % NF][b] = v.w;
        }
    };

    stage(0);
    __syncwarp();

    // ---- prologue: A = bias1 + W1i * x(0) ----
    u64 aI0 = BI1, aI1 = BI1, aF0 = BF1, aF1 = BF1;
    u64 aG0 = BG1, aG1 = BG1, aO0 = BO1, aO1 = BO1;
#pragma unroll
    for (int k = 0; k < NF; k++)
        KSTEP(aI0,aI1,aF0,aF1,aG0,aG1,aO0,aO1,
              &s.w1[k][j], &s.xs[warp][0][k][b0]);

    for (int t = 0; t < SEQ; t++) {
        // restage 4 steps ahead (top of iter: all prior xs reads barrier-fenced)
        if ((t & 3) == 3 && t + 1 < SEQ) stage(t + 1);

        const int p = t & 1, q = p ^ 1;

        // ===== region 1: A += W1h*h1(t-1)  ||  B = bias2 + W2h*h2(t-1) =====
        u64 bI0 = BI2, bI1 = BI2, bF0 = BF2, bF1 = BF2;
        u64 bG0 = BG2, bG1 = BG2, bO0 = BO2, bO1 = BO2;
        const float* h1o = &s.h1d[warp][p][0][b0];
        const float* h2o = &s.h2d[warp][p][0][b0];
#pragma unroll
        for (int k = 0; k < HD; k++) {
            KSTEP(aI0,aI1,aF0,aF1,aG0,aG1,aO0,aO1,
                  &s.w1[NF + k][j], h1o + k * H1R);
            KSTEP(bI0,bI1,bF0,bF1,bG0,bG1,bO0,bO1,
                  &s.w2[HD + k][j], h2o + k * H2R);
        }

        // ---- layer-1 activations ----
        float h1v[4];
        {
            float2 vi0 = unpk(aI0), vi1 = unpk(aI1);
            float2 vf0 = unpk(aF0), vf1 = unpk(aF1);
            float2 vg0 = unpk(aG0), vg1 = unpk(aG1);
            float2 vo0 = unpk(aO0), vo1 = unpk(aO1);
            float iv[4] = {vi0.x, vi0.y, vi1.x, vi1.y};
            float fv[4] = {vf0.x, vf0.y, vf1.x, vf1.y};
            float gv[4] = {vg0.x, vg0.y, vg1.x, vg1.y};
            float ov[4] = {vo0.x, vo0.y, vo1.x, vo1.y};
#pragma unroll
            for (int pp = 0; pp < 4; pp++) {
                float ig = sigf(iv[pp]), fg = sigf(fv[pp]);
                float gg = tanhfast(gv[pp]), og = sigf(ov[pp]);
                float c = fmaf(fg, c1[pp], ig * gg);
                c1[pp] = c;
                h1v[pp] = og * tanhfast(c);
            }
        }
        // write new h1 (other parity buffer; nobody reads it yet -> no pre-barrier)
        *(float4*)&s.h1d[warp][q][j][b0] = make_float4(h1v[0], h1v[1], h1v[2], h1v[3]);
        __syncwarp();   // new h1 visible

        // ===== region 2: B += W2i*relu(h1(t))  ||  A' = bias1 + W1i*x(t+1) =====
        // (t=99 computes a discarded A' from stale-but-valid xs -> branch-free)
        aI0 = BI1; aI1 = BI1; aF0 = BF1; aF1 = BF1;
        aG0 = BG1; aG1 = BG1; aO0 = BO1; aO1 = BO1;
        const float* h1n = &s.h1d[warp][q][0][b0];
        const float* xn  = &s.xs[warp][(t + 1) & 3][0][b0];
#pragma unroll
        for (int k = 0; k < HD; k++) {
            KSTEPR(bI0,bI1,bF0,bF1,bG0,bG1,bO0,bO1,
                   &s.w2[k][j], h1n + k * H1R);
            KSTEP(aI0,aI1,aF0,aF1,aG0,aG1,aO0,aO1,
                  &s.w1[k][j], xn + k * XROWS);
        }
#pragma unroll
        for (int k = HD; k < NF; k++)
            KSTEP(aI0,aI1,aF0,aF1,aG0,aG1,aO0,aO1,
                  &s.w1[k][j], xn + k * XROWS);

        // ---- layer-2 activations ----
        {
            float2 vi0 = unpk(bI0), vi1 = unpk(bI1);
            float2 vf0 = unpk(bF0), vf1 = unpk(bF1);
            float2 vg0 = unpk(bG0), vg1 = unpk(bG1);
            float2 vo0 = unpk(bO0), vo1 = unpk(bO1);
            float iv[4] = {vi0.x, vi0.y, vi1.x, vi1.y};
            float fv[4] = {vf0.x, vf0.y, vf1.x, vf1.y};
            float gv[4] = {vg0.x, vg0.y, vg1.x, vg1.y};
            float ov[4] = {vo0.x, vo0.y, vo1.x, vo1.y};
#pragma unroll
            for (int pp = 0; pp < 4; pp++) {
                float ig = sigf(iv[pp]), fg = sigf(fv[pp]);
                float gg = tanhfast(gv[pp]), og = sigf(ov[pp]);
                float c = fmaf(fg, c2[pp], ig * gg);
                c2[pp] = c;
                h2v[pp] = og * tanhfast(c);
            }
        }
        *(float4*)&s.h2d[warp][q][j][b0] = make_float4(h2v[0], h2v[1], h2v[2], h2v[3]);
        __syncwarp();   // new h2 visible
    }

    // ---- output: relu(h2_last), [B, 16] ----
#pragma unroll
    for (int pp = 0; pp < 4; pp++) {
        out[(warpBatch + b0 + pp) * HD + j] = fmaxf(h2v[pp], 0.f);
    }
}

extern "C" void kernel_launch(void* const* d_in, const int* in_sizes, int n_in,
                              void* d_out, int out_size)
{
    const float* x    = (const float*)d_in[0];
    const float* Wih1 = (const float*)d_in[1];
    const float* Whh1 = (const float*)d_in[2];
    const float* bih1 = (const float*)d_in[3];
    const float* bhh1 = (const float*)d_in[4];
    const float* Wih2 = (const float*)d_in[5];
    const float* Whh2 = (const float*)d_in[6];
    const float* bih2 = (const float*)d_in[7];
    const float* bhh2 = (const float*)d_in[8];
    float* out = (float*)d_out;

    const int smem = (int)sizeof(Smem);   // ~31.5 KB -> 7 CTAs/SM, one wave
    cudaFuncSetAttribute(lstm2_kernel,
                         cudaFuncAttributeMaxDynamicSharedMemorySize, smem);

    // 16384 batch / (2 warps * 8 batch) = 1024 CTAs of 64 threads
    lstm2_kernel<<<1024, 64, smem>>>(x, Wih1, Whh1, bih1, bhh1,
                                     Wih2, Whh2, bih2, bhh2, out);
}

// round 13
// speedup vs baseline: 1.0348x; 1.0348x over previous
#include <cuda_runtime.h>

#define SEQ 100
#define NF  18
#define HD  16
#define TCH 2        // timesteps staged per chunk
#define WPC 2        // warps per CTA (64 threads)
#define BPW 8        // batches per warp (all 8 in every accumulator)

typedef unsigned long long u64;

// lane layout: lane = gp*16 + j; gp=0 -> (i,f) gates, gp=1 -> (g,o) gates
struct __align__(16) Smem {
    float2 w1[NF + HD][32];   // [row][lane]: gp0=(wi,wf), gp1=(wg,wo) for j=lane&15
    float2 w2[2 * HD][32];    // rows 0..15: Wih2, 16..31: Whh2
    float2 bia1[32];          // per-lane combined bias gate-pair
    float2 bia2[32];
    float  xs [WPC][TCH][NF * BPW]; // batch-packed x rows (8 floats = 32B each)
    float  h1d[WPC][HD][BPW];       // batch-packed h1 (pre-relu, recurrence)
    float  h1r[WPC][HD][BPW];       // batch-packed relu(h1)
    float  h2d[WPC][HD][BPW];       // batch-packed h2
};

__device__ __forceinline__ u64 ffma2(u64 a, u64 b, u64 c) {
    u64 d;
    asm("fma.rn.f32x2 %0, %1, %2, %3;" : "=l"(d) : "l"(a), "l"(b), "l"(c));
    return d;
}
__device__ __forceinline__ u64 dup2(float v) {
    u64 d;
    asm("mov.b64 %0, {%1, %1};" : "=l"(d) : "f"(v));
    return d;
}
__device__ __forceinline__ float2 unpk(u64 v) {
    float2 r;
    asm("mov.b64 {%0, %1}, %2;" : "=f"(r.x), "=f"(r.y) : "l"(v));
    return r;
}
__device__ __forceinline__ float sigf(float x) {
    float e = __expf(-x);
    return __fdividef(1.f, 1.f + e);
}
// overflow-safe tanh: tanh(x) = sign(x) * (1 - 2/(exp(2|x|)+1))
__device__ __forceinline__ float tanhfast(float x) {
    float a = fabsf(x);
    float e = __expf(2.f * a);
    float t = 1.f - __fdividef(2.f, e + 1.f);
    return x < 0.f ? -t : t;
}

// one k-row, gate-split: 1 LDS.64 weight (gate pair), 2 ALU dups,
// 2 LDS.128 full-warp-broadcast operand (8 batches), 8 FFMA2
#define KSTEP(P0,P1,P2,P3, Q0,Q1,Q2,Q3, WPTR, OPPTR) do {               \
    float2 _w = *(const float2*)(WPTR);                                  \
    u64 _wp = dup2(_w.x), _wq = dup2(_w.y);                              \
    ulonglong2 _oa = *(const ulonglong2*)(OPPTR);                        \
    ulonglong2 _ob = *(const ulonglong2*)((const float*)(OPPTR) + 4);    \
    P0 = ffma2(_oa.x, _wp, P0);  Q0 = ffma2(_oa.x, _wq, Q0);             \
    P1 = ffma2(_oa.y, _wp, P1);  Q1 = ffma2(_oa.y, _wq, Q1);             \
    P2 = ffma2(_ob.x, _wp, P2);  Q2 = ffma2(_ob.x, _wq, Q2);             \
    P3 = ffma2(_ob.y, _wp, P3);  Q3 = ffma2(_ob.y, _wq, Q3);             \
} while (0)

__global__ void __launch_bounds__(64, 7)
lstm2_kernel(const float* __restrict__ x,
             const float* __restrict__ Wih1, const float* __restrict__ Whh1,
             const float* __restrict__ bih1, const float* __restrict__ bhh1,
             const float* __restrict__ Wih2, const float* __restrict__ Whh2,
             const float* __restrict__ bih2, const float* __restrict__ bhh2,
             float* __restrict__ out)
{
    extern __shared__ Smem sm[];
    Smem& s = sm[0];
    const int tid = threadIdx.x;

    // ---- one-time weight prep: per-lane gate-pair float2 ----
    for (int i = tid; i < (NF + HD) * 32; i += 64) {
        int row = i >> 5, l = i & 31;
        int j = l & 15, gp = l >> 4;
        int g0 = gp * 32 + j, g1 = gp * 32 + 16 + j;   // gate rows: i/g and f/o
        float2 w;
        if (row < NF) {
            int k = row;
            w = make_float2(Wih1[g0 * NF + k], Wih1[g1 * NF + k]);
        } else {
            int k = row - NF;
            w = make_float2(Whh1[g0 * HD + k], Whh1[g1 * HD + k]);
        }
        s.w1[row][l] = w;
    }
    for (int i = tid; i < 2 * HD * 32; i += 64) {
        int row = i >> 5, l = i & 31;
        int j = l & 15, gp = l >> 4;
        int g0 = gp * 32 + j, g1 = gp * 32 + 16 + j;
        float2 w;
        if (row < HD) {
            int k = row;
            w = make_float2(Wih2[g0 * HD + k], Wih2[g1 * HD + k]);
        } else {
            int k = row - HD;
            w = make_float2(Whh2[g0 * HD + k], Whh2[g1 * HD + k]);
        }
        s.w2[row][l] = w;
    }
    if (tid < 32) {
        int l = tid, j = l & 15, gp = l >> 4;
        int g0 = gp * 32 + j, g1 = gp * 32 + 16 + j;
        s.bia1[l] = make_float2(bih1[g0] + bhh1[g0], bih1[g1] + bhh1[g1]);
        s.bia2[l] = make_float2(bih2[g0] + bhh2[g0], bih2[g1] + bhh2[g1]);
    }
    __syncthreads();

    const int warp = tid >> 5;
    const int lane = tid & 31;
    const int gp   = lane >> 4;          // gate-pair half: 0=(i,f), 1=(g,o)
    const int j    = lane & 15;
    const int myb  = gp * 4;             // my 4 batches for activation/state
    const long warpBatch = (long)(blockIdx.x * WPC + warp) * BPW;
    const float* xbase = x + warpBatch * (long)(SEQ * NF);

    // zero h-state (each (j,gp) covers [j][gp*4..gp*4+3], 16B)
    {
        float4 z = make_float4(0.f, 0.f, 0.f, 0.f);
        *(float4*)&s.h1d[warp][j][myb] = z;
        *(float4*)&s.h1r[warp][j][myb] = z;
        *(float4*)&s.h2d[warp][j][myb] = z;
    }
    float c1[4] = {0.f, 0.f, 0.f, 0.f};
    float c2[4] = {0.f, 0.f, 0.f, 0.f};
    float h2v[4] = {0.f, 0.f, 0.f, 0.f};
    __syncwarp();

    // per-lane bias gate-pair, duplicated
    float2 bb1 = s.bia1[lane];
    float2 bb2 = s.bia2[lane];
    const u64 BP1 = dup2(bb1.x), BQ1 = dup2(bb1.y);
    const u64 BP2 = dup2(bb2.x), BQ2 = dup2(bb2.y);

    const unsigned FULL = 0xffffffffu;

    for (int t = 0; t < SEQ; t++) {
        const int tt = t & (TCH - 1);
        if (tt == 0) {
            __syncwarp();     // previous xs reads complete before overwrite
            // stage TCH steps, batch-packed rows; flat layout -> coalesced STS
            for (int idx = lane; idx < TCH * NF * BPW; idx += 32) {
                int tc  = idx / (NF * BPW);
                int rem = idx - tc * (NF * BPW);
                int k = rem >> 3, b = rem & 7;
                s.xs[warp][tc][rem] =
                    xbase[(long)b * (SEQ * NF) + (t + tc) * NF + k];
            }
            __syncwarp();
        }

        // ====== merged region: layer-1 full + layer-2 recurrent ======
        u64 aP0 = BP1, aP1 = BP1, aP2 = BP1, aP3 = BP1;
        u64 aQ0 = BQ1, aQ1 = BQ1, aQ2 = BQ1, aQ3 = BQ1;
        u64 bP0 = BP2, bP1 = BP2, bP2 = BP2, bP3 = BP2;
        u64 bQ0 = BQ2, bQ1 = BQ2, bQ2 = BQ2, bQ3 = BQ2;

#pragma unroll
        for (int k = 0; k < NF; k++)
            KSTEP(aP0,aP1,aP2,aP3, aQ0,aQ1,aQ2,aQ3,
                  &s.w1[k][lane], &s.xs[warp][tt][k * BPW]);
#pragma unroll
        for (int k = 0; k < HD; k++) {
            KSTEP(aP0,aP1,aP2,aP3, aQ0,aQ1,aQ2,aQ3,
                  &s.w1[NF + k][lane], &s.h1d[warp][k][0]);
            KSTEP(bP0,bP1,bP2,bP3, bQ0,bQ1,bQ2,bQ3,
                  &s.w2[HD + k][lane], &s.h2d[warp][k][0]);
        }

        // ---- gate exchange + layer-1 activations (my 4 batches) ----
        float h1v[4];
        {
            u64 t0 = __shfl_xor_sync(FULL, gp ? aP0 : aP2, 16);
            u64 t1 = __shfl_xor_sync(FULL, gp ? aP1 : aP3, 16);
            u64 t2 = __shfl_xor_sync(FULL, gp ? aQ0 : aQ2, 16);
            u64 t3 = __shfl_xor_sync(FULL, gp ? aQ1 : aQ3, 16);
            // my batches: gp0 -> b0-3 (own P/Q = i/f; rx = g/o)
            //             gp1 -> b4-7 (own P/Q = g/o; rx = i/f)
            u64 iA = gp ? t0 : aP0,  iB = gp ? t1 : aP1;
            u64 fA = gp ? t2 : aQ0,  fB = gp ? t3 : aQ1;
            u64 gA = gp ? aP2 : t0,  gB = gp ? aP3 : t1;
            u64 oA = gp ? aQ2 : t2,  oB = gp ? aQ3 : t3;
            float2 vi0 = unpk(iA), vi1 = unpk(iB);
            float2 vf0 = unpk(fA), vf1 = unpk(fB);
            float2 vg0 = unpk(gA), vg1 = unpk(gB);
            float2 vo0 = unpk(oA), vo1 = unpk(oB);
            float iv[4] = {vi0.x, vi0.y, vi1.x, vi1.y};
            float fv[4] = {vf0.x, vf0.y, vf1.x, vf1.y};
            float gv[4] = {vg0.x, vg0.y, vg1.x, vg1.y};
            float ov[4] = {vo0.x, vo0.y, vo1.x, vo1.y};
#pragma unroll
            for (int p = 0; p < 4; p++) {
                float ig = sigf(iv[p]), fg = sigf(fv[p]);
                float gg = tanhfast(gv[p]), og = sigf(ov[p]);
                float c = fmaf(fg, c1[p], ig * gg);
                c1[p] = c;
                h1v[p] = og * tanhfast(c);
            }
        }
        __syncwarp();   // all lanes done reading old h1d / h2d
        *(float4*)&s.h1d[warp][j][myb] = make_float4(h1v[0], h1v[1], h1v[2], h1v[3]);
        *(float4*)&s.h1r[warp][j][myb] = make_float4(fmaxf(h1v[0], 0.f), fmaxf(h1v[1], 0.f),
                                                     fmaxf(h1v[2], 0.f), fmaxf(h1v[3], 0.f));
        __syncwarp();   // new h1 visible

        // ====== layer-2 input part (W_ih2 * relu(h1(t))) ======
#pragma unroll
        for (int k = 0; k < HD; k++)
            KSTEP(bP0,bP1,bP2,bP3, bQ0,bQ1,bQ2,bQ3,
                  &s.w2[k][lane], &s.h1r[warp][k][0]);

        // ---- gate exchange + layer-2 activations ----
        {
            u64 t0 = __shfl_xor_sync(FULL, gp ? bP0 : bP2, 16);
            u64 t1 = __shfl_xor_sync(FULL, gp ? bP1 : bP3, 16);
            u64 t2 = __shfl_xor_sync(FULL, gp ? bQ0 : bQ2, 16);
            u64 t3 = __shfl_xor_sync(FULL, gp ? bQ1 : bQ3, 16);
            u64 iA = gp ? t0 : bP0,  iB = gp ? t1 : bP1;
            u64 fA = gp ? t2 : bQ0,  fB = gp ? t3 : bQ1;
            u64 gA = gp ? bP2 : t0,  gB = gp ? bP3 : t1;
            u64 oA = gp ? bQ2 : t2,  oB = gp ? bQ3 : t3;
            float2 vi0 = unpk(iA), vi1 = unpk(iB);
            float2 vf0 = unpk(fA), vf1 = unpk(fB);
            float2 vg0 = unpk(gA), vg1 = unpk(gB);
            float2 vo0 = unpk(oA), vo1 = unpk(oB);
            float iv[4] = {vi0.x, vi0.y, vi1.x, vi1.y};
            float fv[4] = {vf0.x, vf0.y, vf1.x, vf1.y};
            float gv[4] = {vg0.x, vg0.y, vg1.x, vg1.y};
            float ov[4] = {vo0.x, vo0.y, vo1.x, vo1.y};
#pragma unroll
            for (int p = 0; p < 4; p++) {
                float ig = sigf(iv[p]), fg = sigf(fv[p]);
                float gg = tanhfast(gv[p]), og = sigf(ov[p]);
                float c = fmaf(fg, c2[p], ig * gg);
                c2[p] = c;
                h2v[p] = og * tanhfast(c);
            }
        }
        __syncwarp();   // all lanes done reading old h2d
        *(float4*)&s.h2d[warp][j][myb] = make_float4(h2v[0], h2v[1], h2v[2], h2v[3]);
        __syncwarp();   // new h2 visible
    }

    // ---- output: relu(h2_last), [B, 16]; my 4 batches ----
#pragma unroll
    for (int p = 0; p < 4; p++) {
        out[(warpBatch + myb + p) * HD + j] = fmaxf(h2v[p], 0.f);
    }
}

extern "C" void kernel_launch(void* const* d_in, const int* in_sizes, int n_in,
                              void* d_out, int out_size)
{
    const float* x    = (const float*)d_in[0];
    const float* Wih1 = (const float*)d_in[1];
    const float* Whh1 = (const float*)d_in[2];
    const float* bih1 = (const float*)d_in[3];
    const float* bhh1 = (const float*)d_in[4];
    const float* Wih2 = (const float*)d_in[5];
    const float* Whh2 = (const float*)d_in[6];
    const float* bih2 = (const float*)d_in[7];
    const float* bhh2 = (const float*)d_in[8];
    float* out = (float*)d_out;

    const int smem = (int)sizeof(Smem);   // ~25 KB -> 7 CTAs/SM
    cudaFuncSetAttribute(lstm2_kernel,
                         cudaFuncAttributeMaxDynamicSharedMemorySize, smem);

    // 16384 batch / (2 warps * 8 batch) = 1024 CTAs of 64 threads
    lstm2_kernel<<<1024, 64, smem>>>(x, Wih1, Whh1, bih1, bhh1,
                                     Wih2, Whh2, bih2, bhh2, out);
}

// round 14
// speedup vs baseline: 1.1367x; 1.0984x over previous
#include <cuda_runtime.h>

#define SEQ 100
#define NF  18
#define HD  16
#define TCH 2        // timesteps staged per chunk
#define WPC 2        // warps per CTA (64 threads)
#define BPW 8        // batches per warp (all 8 in every accumulator)

typedef unsigned long long u64;

// lane layout: lane = gp*16 + j; gp=0 -> (i,f) gates, gp=1 -> (g,o) gates
// i,f,o weights/biases are PRE-SCALED by 0.5 so sigmoid(x) = 0.5 + 0.5*tanh(half_pre)
struct __align__(16) Smem {
    float2 w1[NF + HD][32];   // [row][lane]: gp0=(wi/2,wf/2), gp1=(wg,wo/2)
    float2 w2[2 * HD][32];    // rows 0..15: Wih2, 16..31: Whh2
    float2 bia1[32];          // per-lane combined bias gate-pair (same scaling)
    float2 bia2[32];
    float  xs [WPC][TCH][NF * BPW]; // batch-packed x rows (8 floats = 32B each)
    float  h1d[WPC][HD][BPW];       // batch-packed h1 (pre-relu, recurrence)
    float  h1r[WPC][HD][BPW];       // batch-packed relu(h1)
    float  h2d[WPC][HD][BPW];       // batch-packed h2
};

__device__ __forceinline__ u64 ffma2(u64 a, u64 b, u64 c) {
    u64 d;
    asm("fma.rn.f32x2 %0, %1, %2, %3;" : "=l"(d) : "l"(a), "l"(b), "l"(c));
    return d;
}
__device__ __forceinline__ u64 dup2(float v) {
    u64 d;
    asm("mov.b64 %0, {%1, %1};" : "=l"(d) : "f"(v));
    return d;
}
__device__ __forceinline__ float2 unpk(u64 v) {
    float2 r;
    asm("mov.b64 {%0, %1}, %2;" : "=f"(r.x), "=f"(r.y) : "l"(v));
    return r;
}
// MUFU.TANH: single-instruction tanh (sm_75+), abs err ~5e-4
__device__ __forceinline__ float tanha(float x) {
    float r;
    asm("tanh.approx.f32 %0, %1;" : "=f"(r) : "f"(x));
    return r;
}
// sigmoid from HALF pre-activation: sigma(2u) ... pre-act already scaled by 0.5
__device__ __forceinline__ float sig_h(float half_pre) {
    return fmaf(tanha(half_pre), 0.5f, 0.5f);
}

// one k-row, gate-split: 1 LDS.64 weight (gate pair), 2 ALU dups,
// 2 LDS.128 full-warp-broadcast operand (8 batches), 8 FFMA2
#define KSTEP(P0,P1,P2,P3, Q0,Q1,Q2,Q3, WPTR, OPPTR) do {               \
    float2 _w = *(const float2*)(WPTR);                                  \
    u64 _wp = dup2(_w.x), _wq = dup2(_w.y);                              \
    ulonglong2 _oa = *(const ulonglong2*)(OPPTR);                        \
    ulonglong2 _ob = *(const ulonglong2*)((const float*)(OPPTR) + 4);    \
    P0 = ffma2(_oa.x, _wp, P0);  Q0 = ffma2(_oa.x, _wq, Q0);             \
    P1 = ffma2(_oa.y, _wp, P1);  Q1 = ffma2(_oa.y, _wq, Q1);             \
    P2 = ffma2(_ob.x, _wp, P2);  Q2 = ffma2(_ob.x, _wq, Q2);             \
    P3 = ffma2(_ob.y, _wp, P3);  Q3 = ffma2(_ob.y, _wq, Q3);             \
} while (0)

__global__ void __launch_bounds__(64, 7)
lstm2_kernel(const float* __restrict__ x,
             const float* __restrict__ Wih1, const float* __restrict__ Whh1,
             const float* __restrict__ bih1, const float* __restrict__ bhh1,
             const float* __restrict__ Wih2, const float* __restrict__ Whh2,
             const float* __restrict__ bih2, const float* __restrict__ bhh2,
             float* __restrict__ out)
{
    extern __shared__ Smem sm[];
    Smem& s = sm[0];
    const int tid = threadIdx.x;

    // ---- one-time weight prep: per-lane gate-pair float2, i/f/o scaled 0.5 ----
    for (int i = tid; i < (NF + HD) * 32; i += 64) {
        int row = i >> 5, l = i & 31;
        int j = l & 15, gpp = l >> 4;
        int g0 = gpp * 32 + j, g1 = gpp * 32 + 16 + j;   // gates: (i,f) or (g,o)
        float s0 = gpp ? 1.0f : 0.5f;                     // g unscaled, i scaled
        float2 w;
        if (row < NF) {
            int k = row;
            w = make_float2(Wih1[g0 * NF + k] * s0, Wih1[g1 * NF + k] * 0.5f);
        } else {
            int k = row - NF;
            w = make_float2(Whh1[g0 * HD + k] * s0, Whh1[g1 * HD + k] * 0.5f);
        }
        s.w1[row][l] = w;
    }
    for (int i = tid; i < 2 * HD * 32; i += 64) {
        int row = i >> 5, l = i & 31;
        int j = l & 15, gpp = l >> 4;
        int g0 = gpp * 32 + j, g1 = gpp * 32 + 16 + j;
        float s0 = gpp ? 1.0f : 0.5f;
        float2 w;
        if (row < HD) {
            int k = row;
            w = make_float2(Wih2[g0 * HD + k] * s0, Wih2[g1 * HD + k] * 0.5f);
        } else {
            int k = row - HD;
            w = make_float2(Whh2[g0 * HD + k] * s0, Whh2[g1 * HD + k] * 0.5f);
        }
        s.w2[row][l] = w;
    }
    if (tid < 32) {
        int l = tid, j = l & 15, gpp = l >> 4;
        int g0 = gpp * 32 + j, g1 = gpp * 32 + 16 + j;
        float s0 = gpp ? 1.0f : 0.5f;
        s.bia1[l] = make_float2((bih1[g0] + bhh1[g0]) * s0, (bih1[g1] + bhh1[g1]) * 0.5f);
        s.bia2[l] = make_float2((bih2[g0] + bhh2[g0]) * s0, (bih2[g1] + bhh2[g1]) * 0.5f);
    }
    __syncthreads();

    const int warp = tid >> 5;
    const int lane = tid & 31;
    const int gp   = lane >> 4;          // gate-pair half: 0=(i,f), 1=(g,o)
    const int j    = lane & 15;
    const int myb  = gp * 4;             // my 4 batches for activation/state
    const long warpBatch = (long)(blockIdx.x * WPC + warp) * BPW;
    const float* xbase = x + warpBatch * (long)(SEQ * NF);

    // zero h-state (each (j,gp) covers [j][gp*4..gp*4+3], 16B)
    {
        float4 z = make_float4(0.f, 0.f, 0.f, 0.f);
        *(float4*)&s.h1d[warp][j][myb] = z;
        *(float4*)&s.h1r[warp][j][myb] = z;
        *(float4*)&s.h2d[warp][j][myb] = z;
    }
    float c1[4] = {0.f, 0.f, 0.f, 0.f};
    float c2[4] = {0.f, 0.f, 0.f, 0.f};
    float h2v[4] = {0.f, 0.f, 0.f, 0.f};
    __syncwarp();

    // per-lane bias gate-pair, duplicated
    float2 bb1 = s.bia1[lane];
    float2 bb2 = s.bia2[lane];
    const u64 BP1 = dup2(bb1.x), BQ1 = dup2(bb1.y);
    const u64 BP2 = dup2(bb2.x), BQ2 = dup2(bb2.y);

    const unsigned FULL = 0xffffffffu;

    for (int t = 0; t < SEQ; t++) {
        const int tt = t & (TCH - 1);
        if (tt == 0) {
            __syncwarp();     // previous xs reads complete before overwrite
            // stage TCH steps, batch-packed rows; flat layout -> coalesced STS
            for (int idx = lane; idx < TCH * NF * BPW; idx += 32) {
                int tc  = idx / (NF * BPW);
                int rem = idx - tc * (NF * BPW);
                int k = rem >> 3, b = rem & 7;
                s.xs[warp][tc][rem] =
                    xbase[(long)b * (SEQ * NF) + (t + tc) * NF + k];
            }
            __syncwarp();
        }

        // ====== merged region: layer-1 full + layer-2 recurrent ======
        u64 aP0 = BP1, aP1 = BP1, aP2 = BP1, aP3 = BP1;
        u64 aQ0 = BQ1, aQ1 = BQ1, aQ2 = BQ1, aQ3 = BQ1;
        u64 bP0 = BP2, bP1 = BP2, bP2 = BP2, bP3 = BP2;
        u64 bQ0 = BQ2, bQ1 = BQ2, bQ2 = BQ2, bQ3 = BQ2;

#pragma unroll
        for (int k = 0; k < NF; k++)
            KSTEP(aP0,aP1,aP2,aP3, aQ0,aQ1,aQ2,aQ3,
                  &s.w1[k][lane], &s.xs[warp][tt][k * BPW]);
#pragma unroll
        for (int k = 0; k < HD; k++) {
            KSTEP(aP0,aP1,aP2,aP3, aQ0,aQ1,aQ2,aQ3,
                  &s.w1[NF + k][lane], &s.h1d[warp][k][0]);
            KSTEP(bP0,bP1,bP2,bP3, bQ0,bQ1,bQ2,bQ3,
                  &s.w2[HD + k][lane], &s.h2d[warp][k][0]);
        }

        // ---- gate exchange + layer-1 activations (my 4 batches) ----
        float h1v[4];
        {
            u64 t0 = __shfl_xor_sync(FULL, gp ? aP0 : aP2, 16);
            u64 t1 = __shfl_xor_sync(FULL, gp ? aP1 : aP3, 16);
            u64 t2 = __shfl_xor_sync(FULL, gp ? aQ0 : aQ2, 16);
            u64 t3 = __shfl_xor_sync(FULL, gp ? aQ1 : aQ3, 16);
            u64 iA = gp ? t0 : aP0,  iB = gp ? t1 : aP1;
            u64 fA = gp ? t2 : aQ0,  fB = gp ? t3 : aQ1;
            u64 gA = gp ? aP2 : t0,  gB = gp ? aP3 : t1;
            u64 oA = gp ? aQ2 : t2,  oB = gp ? aQ3 : t3;
            float2 vi0 = unpk(iA), vi1 = unpk(iB);
            float2 vf0 = unpk(fA), vf1 = unpk(fB);
            float2 vg0 = unpk(gA), vg1 = unpk(gB);
            float2 vo0 = unpk(oA), vo1 = unpk(oB);
            float iv[4] = {vi0.x, vi0.y, vi1.x, vi1.y};
            float fv[4] = {vf0.x, vf0.y, vf1.x, vf1.y};
            float gv[4] = {vg0.x, vg0.y, vg1.x, vg1.y};
            float ov[4] = {vo0.x, vo0.y, vo1.x, vo1.y};
#pragma unroll
            for (int p = 0; p < 4; p++) {
                float ig = sig_h(iv[p]), fg = sig_h(fv[p]);
                float gg = tanha(gv[p]), og = sig_h(ov[p]);
                float c = fmaf(fg, c1[p], ig * gg);
                c1[p] = c;
                h1v[p] = og * tanha(c);
            }
        }
        __syncwarp();   // all lanes done reading old h1d / h2d
        *(float4*)&s.h1d[warp][j][myb] = make_float4(h1v[0], h1v[1], h1v[2], h1v[3]);
        *(float4*)&s.h1r[warp][j][myb] = make_float4(fmaxf(h1v[0], 0.f), fmaxf(h1v[1], 0.f),
                                                     fmaxf(h1v[2], 0.f), fmaxf(h1v[3], 0.f));
        __syncwarp();   // new h1 visible

        // ====== layer-2 input part (W_ih2 * relu(h1(t))) ======
#pragma unroll
        for (int k = 0; k < HD; k++)
            KSTEP(bP0,bP1,bP2,bP3, bQ0,bQ1,bQ2,bQ3,
                  &s.w2[k][lane], &s.h1r[warp][k][0]);

        // ---- gate exchange + layer-2 activations ----
        {
            u64 t0 = __shfl_xor_sync(FULL, gp ? bP0 : bP2, 16);
            u64 t1 = __shfl_xor_sync(FULL, gp ? bP1 : bP3, 16);
            u64 t2 = __shfl_xor_sync(FULL, gp ? bQ0 : bQ2, 16);
            u64 t3 = __shfl_xor_sync(FULL, gp ? bQ1 : bQ3, 16);
            u64 iA = gp ? t0 : bP0,  iB = gp ? t1 : bP1;
            u64 fA = gp ? t2 : bQ0,  fB = gp ? t3 : bQ1;
            u64 gA = gp ? bP2 : t0,  gB = gp ? bP3 : t1;
            u64 oA = gp ? bQ2 : t2,  oB = gp ? bQ3 : t3;
            float2 vi0 = unpk(iA), vi1 = unpk(iB);
            float2 vf0 = unpk(fA), vf1 = unpk(fB);
            float2 vg0 = unpk(gA), vg1 = unpk(gB);
            float2 vo0 = unpk(oA), vo1 = unpk(oB);
            float iv[4] = {vi0.x, vi0.y, vi1.x, vi1.y};
            float fv[4] = {vf0.x, vf0.y, vf1.x, vf1.y};
            float gv[4] = {vg0.x, vg0.y, vg1.x, vg1.y};
            float ov[4] = {vo0.x, vo0.y, vo1.x, vo1.y};
#pragma unroll
            for (int p = 0; p < 4; p++) {
                float ig = sig_h(iv[p]), fg = sig_h(fv[p]);
                float gg = tanha(gv[p]), og = sig_h(ov[p]);
                float c = fmaf(fg, c2[p], ig * gg);
                c2[p] = c;
                h2v[p] = og * tanha(c);
            }
        }
        __syncwarp();   // all lanes done reading old h2d
        *(float4*)&s.h2d[warp][j][myb] = make_float4(h2v[0], h2v[1], h2v[2], h2v[3]);
        __syncwarp();   // new h2 visible
    }

    // ---- output: relu(h2_last), [B, 16]; my 4 batches ----
#pragma unroll
    for (int p = 0; p < 4; p++) {
        out[(warpBatch + myb + p) * HD + j] = fmaxf(h2v[p], 0.f);
    }
}

extern "C" void kernel_launch(void* const* d_in, const int* in_sizes, int n_in,
                              void* d_out, int out_size)
{
    const float* x    = (const float*)d_in[0];
    const float* Wih1 = (const float*)d_in[1];
    const float* Whh1 = (const float*)d_in[2];
    const float* bih1 = (const float*)d_in[3];
    const float* bhh1 = (const float*)d_in[4];
    const float* Wih2 = (const float*)d_in[5];
    const float* Whh2 = (const float*)d_in[6];
    const float* bih2 = (const float*)d_in[7];
    const float* bhh2 = (const float*)d_in[8];
    float* out = (float*)d_out;

    const int smem = (int)sizeof(Smem);   // ~25 KB -> 7 CTAs/SM
    cudaFuncSetAttribute(lstm2_kernel,
                         cudaFuncAttributeMaxDynamicSharedMemorySize, smem);

    // 16384 batch / (2 warps * 8 batch) = 1024 CTAs of 64 threads
    lstm2_kernel<<<1024, 64, smem>>>(x, Wih1, Whh1, bih1, bhh1,
                                     Wih2, Whh2, bih2, bhh2, out);
}

// round 16
// speedup vs baseline: 1.2040x; 1.0593x over previous
#include <cuda_runtime.h>

#define SEQ 100
#define NF  18
#define HD  16
#define BPW 8        // batches per CTA (one warp-pair)

typedef unsigned long long u64;

// lane layout: lane = gp*16 + j; gp=0 -> (i,f) gates, gp=1 -> (g,o) gates
// i,f,o weights/biases PRE-SCALED by 0.5: sigmoid(x) = 0.5 + 0.5*tanh(half_pre)
struct __align__(16) Smem {
    float2 w1[NF + HD][32];   // prep staging: [row][lane] gate-pair
    float2 w2[2 * HD][32];    // rows 0..15: Wih2, 16..31: Whh2
    float2 bia1[32];
    float2 bia2[32];
    float  xs [2][NF * BPW];  // 2 timestep slots, batch-packed rows (32B each)
    float  h1d[HD][BPW];      // layer-1 recurrence (warp A private)
    float  h1r[2][HD][BPW];   // relu(h1) handoff, double-buffered A -> B
    float  h2d[HD][BPW];      // layer-2 recurrence (warp B private)
};

__device__ __forceinline__ u64 ffma2(u64 a, u64 b, u64 c) {
    u64 d;
    asm("fma.rn.f32x2 %0, %1, %2, %3;" : "=l"(d) : "l"(a), "l"(b), "l"(c));
    return d;
}
__device__ __forceinline__ u64 dup2(float v) {
    u64 d;
    asm("mov.b64 %0, {%1, %1};" : "=l"(d) : "f"(v));
    return d;
}
__device__ __forceinline__ float2 unpk(u64 v) {
    float2 r;
    asm("mov.b64 {%0, %1}, %2;" : "=f"(r.x), "=f"(r.y) : "l"(v));
    return r;
}
// MUFU.TANH (sm_75+)
__device__ __forceinline__ float tanha(float x) {
    float r;
    asm("tanh.approx.f32 %0, %1;" : "=f"(r) : "f"(x));
    return r;
}
// sigmoid from HALF pre-activation (weights pre-scaled by 0.5)
__device__ __forceinline__ float sig_h(float half_pre) {
    return fmaf(tanha(half_pre), 0.5f, 0.5f);
}
__device__ __forceinline__ void ctabar() {
    asm volatile("bar.sync 0, 64;" ::: "memory");
}

// one k-row with REGISTER weight pair: 2 dup2, 2 broadcast LDS.128, 8 FFMA2
#define KSTEPW(W, OPPTR) do {                                            \
    u64 _wp = dup2((W).x), _wq = dup2((W).y);                            \
    ulonglong2 _oa = *(const ulonglong2*)(OPPTR);                        \
    ulonglong2 _ob = *(const ulonglong2*)((const float*)(OPPTR) + 4);    \
    P0 = ffma2(_oa.x, _wp, P0);  Q0 = ffma2(_oa.x, _wq, Q0);             \
    P1 = ffma2(_oa.y, _wp, P1);  Q1 = ffma2(_oa.y, _wq, Q1);             \
    P2 = ffma2(_ob.x, _wp, P2);  Q2 = ffma2(_ob.x, _wq, Q2);             \
    P3 = ffma2(_ob.y, _wp, P3);  Q3 = ffma2(_ob.y, _wq, Q3);             \
} while (0)

// gate exchange across halves + LSTM cell for this lane's 4 batches
#define CELL(CARR, HOUT) do {                                            \
    u64 t0 = __shfl_xor_sync(0xffffffffu, gp ? P0 : P2, 16);             \
    u64 t1 = __shfl_xor_sync(0xffffffffu, gp ? P1 : P3, 16);             \
    u64 t2 = __shfl_xor_sync(0xffffffffu, gp ? Q0 : Q2, 16);             \
    u64 t3 = __shfl_xor_sync(0xffffffffu, gp ? Q1 : Q3, 16);             \
    u64 iA = gp ? t0 : P0,  iB = gp ? t1 : P1;                           \
    u64 fA = gp ? t2 : Q0,  fB = gp ? t3 : Q1;                           \
    u64 gA = gp ? P2 : t0,  gB = gp ? P3 : t1;                           \
    u64 oA = gp ? Q2 : t2,  oB = gp ? Q3 : t3;                           \
    float2 vi0 = unpk(iA), vi1 = unpk(iB);                               \
    float2 vf0 = unpk(fA), vf1 = unpk(fB);                               \
    float2 vg0 = unpk(gA), vg1 = unpk(gB);                               \
    float2 vo0 = unpk(oA), vo1 = unpk(oB);                               \
    float iv[4] = {vi0.x, vi0.y, vi1.x, vi1.y};                          \
    float fv[4] = {vf0.x, vf0.y, vf1.x, vf1.y};                          \
    float gv[4] = {vg0.x, vg0.y, vg1.x, vg1.y};                          \
    float ov[4] = {vo0.x, vo0.y, vo1.x, vo1.y};                          \
    _Pragma("unroll")                                                    \
    for (int p = 0; p < 4; p++) {                                        \
        float ig = sig_h(iv[p]), fg = sig_h(fv[p]);                      \
        float gg = tanha(gv[p]), og = sig_h(ov[p]);                      \
        float c = fmaf(fg, (CARR)[p], ig * gg);                          \
        (CARR)[p] = c;                                                   \
        (HOUT)[p] = og * tanha(c);                                       \
    }                                                                    \
} while (0)

__global__ void __launch_bounds__(64, 7)
lstm2_kernel(const float* __restrict__ x,
             const float* __restrict__ Wih1, const float* __restrict__ Whh1,
             const float* __restrict__ bih1, const float* __restrict__ bhh1,
             const float* __restrict__ Wih2, const float* __restrict__ Whh2,
             const float* __restrict__ bih2, const float* __restrict__ bhh2,
             float* __restrict__ out)
{
    extern __shared__ Smem sm[];
    Smem& s = sm[0];
    const int tid = threadIdx.x;

    // ---- one-time weight prep into smem tables (i/f/o scaled by 0.5) ----
    for (int i = tid; i < (NF + HD) * 32; i += 64) {
        int row = i >> 5, l = i & 31;
        int jj = l & 15, gpp = l >> 4;
        int g0 = gpp * 32 + jj, g1 = gpp * 32 + 16 + jj;
        float s0 = gpp ? 1.0f : 0.5f;
        float2 w;
        if (row < NF) {
            int k = row;
            w = make_float2(Wih1[g0 * NF + k] * s0, Wih1[g1 * NF + k] * 0.5f);
        } else {
            int k = row - NF;
            w = make_float2(Whh1[g0 * HD + k] * s0, Whh1[g1 * HD + k] * 0.5f);
        }
        s.w1[row][l] = w;
    }
    for (int i = tid; i < 2 * HD * 32; i += 64) {
        int row = i >> 5, l = i & 31;
        int jj = l & 15, gpp = l >> 4;
        int g0 = gpp * 32 + jj, g1 = gpp * 32 + 16 + jj;
        float s0 = gpp ? 1.0f : 0.5f;
        float2 w;
        if (row < HD) {
            int k = row;
            w = make_float2(Wih2[g0 * HD + k] * s0, Wih2[g1 * HD + k] * 0.5f);
        } else {
            int k = row - HD;
            w = make_float2(Whh2[g0 * HD + k] * s0, Whh2[g1 * HD + k] * 0.5f);
        }
        s.w2[row][l] = w;
    }
    if (tid < 32) {
        int l = tid, jj = l & 15, gpp = l >> 4;
        int g0 = gpp * 32 + jj, g1 = gpp * 32 + 16 + jj;
        float s0 = gpp ? 1.0f : 0.5f;
        s.bia1[l] = make_float2((bih1[g0] + bhh1[g0]) * s0, (bih1[g1] + bhh1[g1]) * 0.5f);
        s.bia2[l] = make_float2((bih2[g0] + bhh2[g0]) * s0, (bih2[g1] + bhh2[g1]) * 0.5f);
    }
    __syncthreads();

    const int wA   = (tid < 32);
    const int lane = tid & 31;
    const int gp   = lane >> 4;
    const int j    = lane & 15;
    const int myb  = gp * 4;
    const long ctaBatch = (long)blockIdx.x * BPW;

    if (wA) {
        // =========================== WARP A: layer 1 ===========================
        const float* xbase = x + ctaBatch * (long)(SEQ * NF);

        float2 w1r[NF + HD];
#pragma unroll
        for (int r = 0; r < NF + HD; r++) w1r[r] = s.w1[r][lane];
        float2 bb = s.bia1[lane];
        const u64 BP = dup2(bb.x), BQ = dup2(bb.y);

        // zero h1 state
        *(float4*)&s.h1d[j][myb] = make_float4(0.f, 0.f, 0.f, 0.f);
        __syncwarp();

        float c1[4] = {0.f, 0.f, 0.f, 0.f};
        float h1v[4];

        for (int t = 0; t <= SEQ; t++) {
            if (t < SEQ) {
                if ((t & 1) == 0) {
                    __syncwarp();
                    // stage x(t) -> slot 0, x(t+1) -> slot 1 (batch-packed rows)
                    for (int idx = lane; idx < 2 * NF * BPW; idx += 32) {
                        int tc  = idx / (NF * BPW);
                        int rem = idx - tc * (NF * BPW);
                        int k = rem >> 3, b = rem & 7;
                        s.xs[tc][rem] =
                            xbase[(long)b * (SEQ * NF) + (t + tc) * NF + k];
                    }
                    __syncwarp();
                }

                u64 P0 = BP, P1 = BP, P2 = BP, P3 = BP;
                u64 Q0 = BQ, Q1 = BQ, Q2 = BQ, Q3 = BQ;
                const float* xr = &s.xs[t & 1][0];
#pragma unroll
                for (int k = 0; k < NF; k++)
                    KSTEPW(w1r[k], xr + k * BPW);
#pragma unroll
                for (int k = 0; k < HD; k++)
                    KSTEPW(w1r[NF + k], &s.h1d[k][0]);

                CELL(c1, h1v);

                __syncwarp();   // all A lanes done reading old h1d
                *(float4*)&s.h1d[j][myb] =
                    make_float4(h1v[0], h1v[1], h1v[2], h1v[3]);
                *(float4*)&s.h1r[t & 1][j][myb] =
                    make_float4(fmaxf(h1v[0], 0.f), fmaxf(h1v[1], 0.f),
                                fmaxf(h1v[2], 0.f), fmaxf(h1v[3], 0.f));
            }
            ctabar();
        }
    } else {
        // =========================== WARP B: layer 2 ===========================
        float2 w2r[2 * HD];
#pragma unroll
        for (int r = 0; r < 2 * HD; r++) w2r[r] = s.w2[r][lane];
        float2 bb = s.bia2[lane];
        const u64 BP2 = dup2(bb.x), BQ2 = dup2(bb.y);

        // zero h2 state
        *(float4*)&s.h2d[j][myb] = make_float4(0.f, 0.f, 0.f, 0.f);
        __syncwarp();

        float c2[4] = {0.f, 0.f, 0.f, 0.f};
        float h2v[4] = {0.f, 0.f, 0.f, 0.f};

        for (int t = 0; t <= SEQ; t++) {
            if (t > 0) {
                const int tb = t - 1;     // step being computed by B
                u64 P0 = BP2, P1 = BP2, P2 = BP2, P3 = BP2;
                u64 Q0 = BQ2, Q1 = BQ2, Q2 = BQ2, Q3 = BQ2;
                // recurrent part first (matches R14 accumulation order)
#pragma unroll
                for (int k = 0; k < HD; k++)
                    KSTEPW(w2r[HD + k], &s.h2d[k][0]);
                const float* hr = &s.h1r[tb & 1][0][0];
#pragma unroll
                for (int k = 0; k < HD; k++)
                    KSTEPW(w2r[k], hr + k * BPW);

                CELL(c2, h2v);

                __syncwarp();   // all B lanes done reading old h2d
                *(float4*)&s.h2d[j][myb] =
                    make_float4(h2v[0], h2v[1], h2v[2], h2v[3]);
            }
            ctabar();
        }

        // ---- output: relu(h2_last), [B, 16] ----
#pragma unroll
        for (int p = 0; p < 4; p++) {
            out[(ctaBatch + myb + p) * HD + j] = fmaxf(h2v[p], 0.f);
        }
    }
}

extern "C" void kernel_launch(void* const* d_in, const int* in_sizes, int n_in,
                              void* d_out, int out_size)
{
    const float* x    = (const float*)d_in[0];
    const float* Wih1 = (const float*)d_in[1];
    const float* Whh1 = (const float*)d_in[2];
    const float* bih1 = (const float*)d_in[3];
    const float* bhh1 = (const float*)d_in[4];
    const float* Wih2 = (const float*)d_in[5];
    const float* Whh2 = (const float*)d_in[6];
    const float* bih2 = (const float*)d_in[7];
    const float* bhh2 = (const float*)d_in[8];
    float* out = (float*)d_out;

    const int smem = (int)sizeof(Smem);   // ~20.6 KB
    cudaFuncSetAttribute(lstm2_kernel,
                         cudaFuncAttributeMaxDynamicSharedMemorySize, smem);

    // 16384 batch / 8 per CTA = 2048 CTAs of 64 threads (warp A + warp B)
    lstm2_kernel<<<2048, 64, smem>>>(x, Wih1, Whh1, bih1, bhh1,
                                     Wih2, Whh2, bih2, bhh2, out);
}